// round 10
// baseline (speedup 1.0000x reference)
#include <cuda_runtime.h>
#include <math.h>

// Cross-block reduction scratch (zero at module load; last block re-zeroes
// after each launch so every graph replay starts from a clean state).
__device__ double g_sum;
__device__ unsigned int g_done;

__device__ __forceinline__ float row_loss(float4 p, float4 t)
{
    const float DELTA = 0.1f;
    const float inv3  = 1.0f / 3.0f;

    float mp = (p.x + p.y + p.z + p.w) * 0.25f;
    float mt = (t.x + t.y + t.z + t.w) * 0.25f;

    float dpx = p.x - mp, dpy = p.y - mp, dpz = p.z - mp, dpw = p.w - mp;
    float dtx = t.x - mt, dty = t.y - mt, dtz = t.z - mt, dtw = t.w - mt;

    float var_p = (dpx*dpx + dpy*dpy + dpz*dpz + dpw*dpw) * inv3;
    float var_t = (dtx*dtx + dty*dty + dtz*dtz + dtw*dtw) * inv3;
    float cov   = (dpx*dtx + dpy*dty + dpz*dtz + dpw*dtw) * inv3;

    float a1 = 2.0f * mp * mt + DELTA;
    float a2 = 2.0f * cov + DELTA;
    float b1 = mp * mp + mt * mt + DELTA;
    float b2 = var_p + var_t + DELTA;

    // rcp.approx+mul: ~2 ulp on O(1) operands, far inside the 1e-3 tolerance.
    return 1.0f - __fdividef(a1 * a2, b1 * b2 + DELTA);
}

__global__ void __launch_bounds__(256)
ssim_loss_kernel(const float4* __restrict__ pred,
                 const float4* __restrict__ target,
                 float* __restrict__ out,
                 int n_rows)
{
    float local = 0.0f;
    const int stride = gridDim.x * blockDim.x;

    // Plain grid-stride with L2-only loads: measured fastest of 7 memory
    // engines tried (LDG.128 cs/cg/default, unroll x2/x4, TMA bulk, LDG.256,
    // L2 prefetch) — all plateau at the ~5.3 TB/s dual-stream HBM ceiling.
    for (int i = blockIdx.x * blockDim.x + threadIdx.x; i < n_rows; i += stride) {
        float4 p = __ldcg(&pred[i]);
        float4 t = __ldcg(&target[i]);
        local += row_loss(p, t);
    }

    // Warp reduction
    #pragma unroll
    for (int off = 16; off > 0; off >>= 1)
        local += __shfl_down_sync(0xFFFFFFFFu, local, off);

    __shared__ float warp_sums[8];
    int lane = threadIdx.x & 31;
    int wid  = threadIdx.x >> 5;
    if (lane == 0) warp_sums[wid] = local;
    __syncthreads();

    if (wid == 0) {
        float bs = (lane < 8) ? warp_sums[lane] : 0.0f;
        #pragma unroll
        for (int off = 4; off > 0; off >>= 1)
            bs += __shfl_down_sync(0xFFFFFFFFu, bs, off);

        if (lane == 0) {
            atomicAdd(&g_sum, (double)bs);
            __threadfence();
            unsigned int prev = atomicAdd(&g_done, 1u);
            if (prev == gridDim.x - 1) {
                // Last block: finalize and reset state for the next replay.
                double mean = g_sum / (double)n_rows;
                float r = (float)mean;
                if (isnan(r)) r = 1.0f;   // reference NaN fallback == 1.0
                out[0] = r;
                g_sum = 0.0;
                g_done = 0u;
                __threadfence();
            }
        }
    }
}

extern "C" void kernel_launch(void* const* d_in, const int* in_sizes, int n_in,
                              void* d_out, int out_size)
{
    const float4* pred   = (const float4*)d_in[0];
    const float4* target = (const float4*)d_in[1];
    float* out = (float*)d_out;

    int n_rows = in_sizes[0] / 4;   // [N, 4] float32 -> N rows of float4

    const int threads = 256;
    int blocks = 148 * 16;          // best-measured grid (2368), 2 exact waves
    int max_blocks = (n_rows + threads - 1) / threads;
    if (blocks > max_blocks) blocks = max_blocks;

    ssim_loss_kernel<<<blocks, threads>>>(pred, target, out, n_rows);
}

// round 11
// speedup vs baseline: 1.0515x; 1.0515x over previous
#include <cuda_runtime.h>
#include <math.h>

// Cross-block reduction scratch (zero at module load; last block re-zeroes
// after each launch so every graph replay starts from a clean state).
__device__ double g_sum;
__device__ unsigned int g_done;

__device__ __forceinline__ float row_loss(float4 p, float4 t)
{
    const float DELTA = 0.1f;
    const float inv3  = 1.0f / 3.0f;

    float mp = (p.x + p.y + p.z + p.w) * 0.25f;
    float mt = (t.x + t.y + t.z + t.w) * 0.25f;

    float dpx = p.x - mp, dpy = p.y - mp, dpz = p.z - mp, dpw = p.w - mp;
    float dtx = t.x - mt, dty = t.y - mt, dtz = t.z - mt, dtw = t.w - mt;

    float var_p = (dpx*dpx + dpy*dpy + dpz*dpz + dpw*dpw) * inv3;
    float var_t = (dtx*dtx + dty*dty + dtz*dtz + dtw*dtw) * inv3;
    float cov   = (dpx*dtx + dpy*dty + dpz*dtz + dpw*dtw) * inv3;

    float a1 = 2.0f * mp * mt + DELTA;
    float a2 = 2.0f * cov + DELTA;
    float b1 = mp * mp + mt * mt + DELTA;
    float b2 = var_p + var_t + DELTA;

    // rcp.approx+mul: ~2 ulp on O(1) operands, far inside the 1e-3 tolerance.
    return 1.0f - __fdividef(a1 * a2, b1 * b2 + DELTA);
}

__global__ void __launch_bounds__(256, 8)
ssim_loss_kernel(const float4* __restrict__ pred,
                 const float4* __restrict__ target,
                 float* __restrict__ out,
                 int n_rows)
{
    float local = 0.0f;
    const int stride = gridDim.x * blockDim.x;

    // Single-wave grid-stride (1184 CTAs = 8/SM resident simultaneously):
    // no wave transition, SMs stay busy start-to-finish.
    for (int i = blockIdx.x * blockDim.x + threadIdx.x; i < n_rows; i += stride) {
        float4 p = __ldcg(&pred[i]);
        float4 t = __ldcg(&target[i]);
        local += row_loss(p, t);
    }

    // Warp reduction
    #pragma unroll
    for (int off = 16; off > 0; off >>= 1)
        local += __shfl_down_sync(0xFFFFFFFFu, local, off);

    __shared__ float warp_sums[8];
    int lane = threadIdx.x & 31;
    int wid  = threadIdx.x >> 5;
    if (lane == 0) warp_sums[wid] = local;
    __syncthreads();

    if (wid == 0) {
        float bs = (lane < 8) ? warp_sums[lane] : 0.0f;
        #pragma unroll
        for (int off = 4; off > 0; off >>= 1)
            bs += __shfl_down_sync(0xFFFFFFFFu, bs, off);

        if (lane == 0) {
            atomicAdd(&g_sum, (double)bs);
            __threadfence();
            unsigned int prev = atomicAdd(&g_done, 1u);
            if (prev == gridDim.x - 1) {
                // Last block: finalize and reset state for the next replay.
                double mean = g_sum / (double)n_rows;
                float r = (float)mean;
                if (isnan(r)) r = 1.0f;   // reference NaN fallback == 1.0
                out[0] = r;
                g_sum = 0.0;
                g_done = 0u;
                __threadfence();
            }
        }
    }
}

extern "C" void kernel_launch(void* const* d_in, const int* in_sizes, int n_in,
                              void* d_out, int out_size)
{
    const float4* pred   = (const float4*)d_in[0];
    const float4* target = (const float4*)d_in[1];
    float* out = (float*)d_out;

    int n_rows = in_sizes[0] / 4;   // [N, 4] float32 -> N rows of float4

    const int threads = 256;
    int blocks = 148 * 8;           // exactly one full-occupancy wave (1184)
    int max_blocks = (n_rows + threads - 1) / threads;
    if (blocks > max_blocks) blocks = max_blocks;

    ssim_loss_kernel<<<blocks, threads>>>(pred, target, out, n_rows);
}

// round 15
// speedup vs baseline: 1.0931x; 1.0395x over previous
#include <cuda_runtime.h>
#include <math.h>

// Cross-block reduction scratch (zero at module load; last block re-zeroes
// after each launch so every graph replay starts from a clean state).
__device__ double g_sum;
__device__ unsigned int g_done;

__device__ __forceinline__ float row_loss(float4 p, float4 t)
{
    const float DELTA = 0.1f;
    const float inv3  = 1.0f / 3.0f;

    float mp = (p.x + p.y + p.z + p.w) * 0.25f;
    float mt = (t.x + t.y + t.z + t.w) * 0.25f;

    float dpx = p.x - mp, dpy = p.y - mp, dpz = p.z - mp, dpw = p.w - mp;
    float dtx = t.x - mt, dty = t.y - mt, dtz = t.z - mt, dtw = t.w - mt;

    float var_p = (dpx*dpx + dpy*dpy + dpz*dpz + dpw*dpw) * inv3;
    float var_t = (dtx*dtx + dty*dty + dtz*dtz + dtw*dtw) * inv3;
    float cov   = (dpx*dtx + dpy*dty + dpz*dtz + dpw*dtw) * inv3;

    float a1 = 2.0f * mp * mt + DELTA;
    float a2 = 2.0f * cov + DELTA;
    float b1 = mp * mp + mt * mt + DELTA;
    float b2 = var_p + var_t + DELTA;

    // rcp.approx+mul: ~2 ulp on O(1) operands, far inside the 1e-3 tolerance.
    return 1.0f - __fdividef(a1 * a2, b1 * b2 + DELTA);
}

__global__ void __launch_bounds__(256, 8)
ssim_loss_kernel(const float4* __restrict__ pred,
                 const float4* __restrict__ target,
                 float* __restrict__ out,
                 int n_rows)
{
    float local = 0.0f;
    const int stride = gridDim.x * blockDim.x;

    // Single-wave grid-stride across ALL 152 GB300 SMs (8 CTAs/SM resident):
    // no wave transition, every SM busy start-to-finish.
    for (int i = blockIdx.x * blockDim.x + threadIdx.x; i < n_rows; i += stride) {
        float4 p = __ldcg(&pred[i]);
        float4 t = __ldcg(&target[i]);
        local += row_loss(p, t);
    }

    // Warp reduction
    #pragma unroll
    for (int off = 16; off > 0; off >>= 1)
        local += __shfl_down_sync(0xFFFFFFFFu, local, off);

    __shared__ float warp_sums[8];
    int lane = threadIdx.x & 31;
    int wid  = threadIdx.x >> 5;
    if (lane == 0) warp_sums[wid] = local;
    __syncthreads();

    if (wid == 0) {
        float bs = (lane < 8) ? warp_sums[lane] : 0.0f;
        #pragma unroll
        for (int off = 4; off > 0; off >>= 1)
            bs += __shfl_down_sync(0xFFFFFFFFu, bs, off);

        if (lane == 0) {
            atomicAdd(&g_sum, (double)bs);
            __threadfence();
            unsigned int prev = atomicAdd(&g_done, 1u);
            if (prev == gridDim.x - 1) {
                // Last block: finalize and reset state for the next replay.
                double mean = g_sum / (double)n_rows;
                float r = (float)mean;
                if (isnan(r)) r = 1.0f;   // reference NaN fallback == 1.0
                out[0] = r;
                g_sum = 0.0;
                g_done = 0u;
                __threadfence();
            }
        }
    }
}

extern "C" void kernel_launch(void* const* d_in, const int* in_sizes, int n_in,
                              void* d_out, int out_size)
{
    const float4* pred   = (const float4*)d_in[0];
    const float4* target = (const float4*)d_in[1];
    float* out = (float*)d_out;

    int n_rows = in_sizes[0] / 4;   // [N, 4] float32 -> N rows of float4

    const int threads = 256;
    int blocks = 152 * 8;           // GB300 has 152 SMs: one full wave = 1216
    int max_blocks = (n_rows + threads - 1) / threads;
    if (blocks > max_blocks) blocks = max_blocks;

    ssim_loss_kernel<<<blocks, threads>>>(pred, target, out, n_rows);
}